// round 8
// baseline (speedup 1.0000x reference)
#include <cuda_runtime.h>
#include <cstdint>

// ---------------- problem / tiling constants ----------------
#define NN 8192
#define SS 3
#define DD 32
#define KSPLIT 8
#define KPER (NN / KSPLIT)            // 1024 K per item
#define BM 128
#define BK 32
#define SPI (KPER / BK)               // 32 stages per item (multiple of 4!)
#define NMT (NN / BM)                 // 64 M-tiles
#define NITEMS (NMT * SS * KSPLIT)    // 1536 work items

// smem layout (floats). Row stride 36 -> fragment bank = (4r+c)%32, conflict-free;
// 144B rows keep 16B cp.async alignment.
#define SROW 36
#define SA_FLOATS (BM * SROW)                  // 4608
#define SB_FLOATS (DD * SROW)                  // 1152
#define ABASE 0
#define BBASE (4 * SA_FLOATS)                  // 4 stages
#define SMEM_FLOATS (BBASE + 4 * SB_FLOATS)    // 23040 floats -> 92160 B

// ---------------- scratch (no cudaMalloc allowed) ----------------
__device__ float g_preT[SS * DD * NN];            // preT[s][o][n], tf32-rn, 3 MB
__device__ float g_part[SS * KSPLIT][NN * DD];    // K-split partials
__device__ int   g_ctr;                           // work-steal counter

// tf32 round-to-nearest: +0x1000 into bit 12; MMA HW truncates low 13 bits.
__device__ __forceinline__ uint32_t tf32rn(uint32_t u) { return u + 0x1000u; }

// ---------------- cp.async helpers ----------------
__device__ __forceinline__ void cp16(uint32_t saddr, const float* g) {
    asm volatile("cp.async.cg.shared.global [%0], [%1], 16;"
                 :: "r"(saddr), "l"(g) : "memory");
}
__device__ __forceinline__ void cp_commit() {
    asm volatile("cp.async.commit_group;" ::: "memory");
}
__device__ __forceinline__ void cp_wait2() {
    asm volatile("cp.async.wait_group 2;" ::: "memory");
}

// ---------------------------------------------------------------------------
// Kernel 1: preT[s][o][n] = rn_tf32( b[s][o] + sum_i x[n][i]*W[s][i][o] )
// One output per thread; grid (256, 4, 3) tiny blocks; also resets g_ctr.
// ---------------------------------------------------------------------------
__global__ __launch_bounds__(256) void pre_kernel(const float* __restrict__ x,
                                                  const float* __restrict__ W,
                                                  const float* __restrict__ b,
                                                  int nworkers) {
    if (blockIdx.x == 0 && blockIdx.y == 0 && blockIdx.z == 0 && threadIdx.x == 0)
        g_ctr = nworkers;

    __shared__ float sx[32 * 33];
    __shared__ float sWs[32 * 8];
    __shared__ float sb8[8];

    int s = blockIdx.z, o0 = blockIdx.y * 8, n0 = blockIdx.x * 32;
    int t = threadIdx.x;

    for (int i = t; i < 32 * DD; i += 256) {
        int row = i >> 5, col = i & 31;
        sx[row * 33 + col] = x[(size_t)n0 * DD + i];
    }
    {
        int row = t >> 3, oc = t & 7;
        sWs[row * 8 + oc] = W[s * DD * DD + row * DD + o0 + oc];
    }
    if (t < 8) sb8[t] = b[s * DD + o0 + t];
    __syncthreads();

    int nl = t & 31, oj = t >> 5;
    float acc = sb8[oj];
#pragma unroll
    for (int i = 0; i < DD; i++)
        acc = fmaf(sx[nl * 33 + i], sWs[i * 8 + oj], acc);
    g_preT[(size_t)(s * DD + o0 + oj) * NN + n0 + nl] =
        __uint_as_float(tf32rn(__float_as_uint(acc)));
}

// ---------------------------------------------------------------------------
// Kernel 2: persistent work-stealing tf32 mma.sync GEMM, flattened cp.async
// pipeline (3 stages lead, 4 buffers, ONE barrier per stage, continuous
// across item boundaries).
// ---------------------------------------------------------------------------
__global__ void __launch_bounds__(256, 2) gemm_kernel(const float* __restrict__ adj) {
    extern __shared__ float smem[];
    __shared__ int s_next;
    const uint32_t sbase = (uint32_t)__cvta_generic_to_shared(smem);

    const int t = threadIdx.x;
    const int wid = t >> 5, lane = t & 31;
    const int r = lane >> 2, c = lane & 3;
    const int m0w = wid * 16;

    auto decode = [&](int it, const float*& aB, const float*& bB, int& s, int& z, int& mt) {
        mt = it & (NMT - 1);
        int sz = it >> 6;
        s = sz % SS; z = sz / SS;
        aB = adj + ((size_t)(s * NN + mt * BM)) * NN + (size_t)z * KPER;
        bB = g_preT + (size_t)s * DD * NN + (size_t)z * KPER;
    };

    // issue stage st (within its item) from bases (aB,bB); buffer = st & 3
    // (valid across items because SPI % 4 == 0).
    auto issue = [&](const float* aB, const float* bB, int st) {
        int buf = st & 3;
        uint32_t sa = sbase + (ABASE + buf * SA_FLOATS) * 4;
        uint32_t sb = sbase + (BBASE + buf * SB_FLOATS) * 4;
#pragma unroll
        for (int i = 0; i < 4; i++) {
            int idx = i * 256 + t;
            int row = idx >> 3, gr = idx & 7;
            cp16(sa + (row * SROW + gr * 4) * 4,
                 aB + (size_t)row * NN + st * BK + gr * 4);
        }
        int brow = t >> 3, bgr = t & 7;
        cp16(sb + (brow * SROW + bgr * 4) * 4,
             bB + (size_t)brow * NN + st * BK + bgr * 4);
    };

    auto compute = [&](int st, float (&acc)[4][4]) {
        int buf = st & 3;
        const uint32_t* sA = reinterpret_cast<const uint32_t*>(smem + ABASE + buf * SA_FLOATS);
        const uint32_t* sB = reinterpret_cast<const uint32_t*>(smem + BBASE + buf * SB_FLOATS);
#pragma unroll
        for (int k8 = 0; k8 < BK / 8; k8++) {
            int k0 = k8 * 8;
            uint32_t a0 = tf32rn(sA[(m0w + r) * SROW + k0 + c]);
            uint32_t a1 = tf32rn(sA[(m0w + r + 8) * SROW + k0 + c]);
            uint32_t a2 = tf32rn(sA[(m0w + r) * SROW + k0 + c + 4]);
            uint32_t a3 = tf32rn(sA[(m0w + r + 8) * SROW + k0 + c + 4]);
#pragma unroll
            for (int nt = 0; nt < 4; nt++) {
                uint32_t b0 = sB[(nt * 8 + r) * SROW + k0 + c];
                uint32_t b1 = sB[(nt * 8 + r) * SROW + k0 + c + 4];
                asm volatile(
                    "mma.sync.aligned.m16n8k8.row.col.f32.tf32.tf32.f32 "
                    "{%0,%1,%2,%3}, {%4,%5,%6,%7}, {%8,%9}, {%0,%1,%2,%3};"
                    : "+f"(acc[nt][0]), "+f"(acc[nt][1]),
                      "+f"(acc[nt][2]), "+f"(acc[nt][3])
                    : "r"(a0), "r"(a1), "r"(a2), "r"(a3), "r"(b0), "r"(b1));
            }
        }
    };

    // ---- first item (static) + pipeline priming ----
    int cur = blockIdx.x;                 // grid <= NITEMS guaranteed by host
    const float *aB, *bB; int s, z, mt;
    decode(cur, aB, bB, s, z, mt);
    issue(aB, bB, 0); cp_commit();
    issue(aB, bB, 1); cp_commit();
    issue(aB, bB, 2); cp_commit();

    while (true) {
        float acc[4][4];
#pragma unroll
        for (int nt = 0; nt < 4; nt++)
#pragma unroll
            for (int j = 0; j < 4; j++) acc[nt][j] = 0.0f;

        const float *naB = nullptr, *nbB = nullptr;
        int ns = 0, nz = 0, nmt = 0, nxt = NITEMS;

#pragma unroll 1
        for (int st = 0; st < SPI; st++) {
            cp_wait2();                   // group st retired (this thread)
            __syncthreads();              // visible to all; also frees buf (st+3)&3
            if (st == SPI - 4 && t == 0) s_next = atomicAdd(&g_ctr, 1);
            if (st + 3 < SPI) {
                issue(aB, bB, st + 3);
            } else {
                if (st == SPI - 3) {      // s_next written last iter, fenced by barrier
                    nxt = s_next;
                    if (nxt < NITEMS) decode(nxt, naB, nbB, ns, nz, nmt);
                }
                if (nxt < NITEMS) issue(naB, nbB, st + 3 - SPI);
            }
            cp_commit();                  // one group per iter, even if empty
            compute(st, acc);
        }

        // ---- epilogue: deterministic partial store for item `cur` ----
        float* po = g_part[s * KSPLIT + z];
#pragma unroll
        for (int nt = 0; nt < 4; nt++) {
#pragma unroll
            for (int h = 0; h < 2; h++) {
                int m = mt * BM + m0w + r + 8 * h;
                float2 v = make_float2(acc[nt][2 * h], acc[nt][2 * h + 1]);
                *reinterpret_cast<float2*>(&po[(size_t)m * DD + nt * 8 + 2 * c]) = v;
            }
        }

        if (nxt >= NITEMS) break;
        cur = nxt; aB = naB; bB = nbB; s = ns; z = nz; mt = nmt;
    }
}

// ---------------------------------------------------------------------------
// Kernel 3: out = relu(sum over 24 partials)
// ---------------------------------------------------------------------------
__global__ __launch_bounds__(256) void reduce_kernel(float* __restrict__ out) {
    int i = blockIdx.x * 256 + threadIdx.x;
    float4 a = make_float4(0.f, 0.f, 0.f, 0.f);
#pragma unroll
    for (int p = 0; p < SS * KSPLIT; p++) {
        float4 v = reinterpret_cast<const float4*>(g_part[p])[i];
        a.x += v.x; a.y += v.y; a.z += v.z; a.w += v.w;
    }
    a.x = fmaxf(a.x, 0.f); a.y = fmaxf(a.y, 0.f);
    a.z = fmaxf(a.z, 0.f); a.w = fmaxf(a.w, 0.f);
    reinterpret_cast<float4*>(out)[i] = a;
}

// ---------------------------------------------------------------------------
// Launch
// ---------------------------------------------------------------------------
extern "C" void kernel_launch(void* const* d_in, const int* in_sizes, int n_in,
                              void* d_out, int out_size) {
    const float* x   = (const float*)d_in[0];   // [8192, 32]
    const float* adj = (const float*)d_in[1];   // [3, 8192, 8192]
    const float* W   = (const float*)d_in[2];   // [3, 32, 32]
    const float* b   = (const float*)d_in[3];   // [3, 32]
    float* out = (float*)d_out;                 // [8192, 32]

    cudaFuncSetAttribute(gemm_kernel, cudaFuncAttributeMaxDynamicSharedMemorySize,
                         SMEM_FLOATS * 4);
    int sms = 148;
    cudaDeviceGetAttribute(&sms, cudaDevAttrMultiProcessorCount, 0);
    int workers = 2 * sms;
    if (workers > NITEMS) workers = NITEMS;

    pre_kernel<<<dim3(NN / 32, 4, SS), 256>>>(x, W, b, workers);
    gemm_kernel<<<workers, 256, SMEM_FLOATS * 4>>>(adj);
    reduce_kernel<<<(NN * DD / 4) / 256, 256>>>(out);
}